// round 10
// baseline (speedup 1.0000x reference)
#include <cuda_runtime.h>
#include <cuda_fp16.h>
#include <math.h>
#include <stdint.h>

// Problem constants
#define BATCH 256
#define DIM   1024
#define L_IM  37
#define L_S   33
#define LI    36
#define LS    30
#define MARGIN 0.2f

#define MROWS  (BATCH*LI)     // 9216
#define NCOLS  (BATCH*LS)     // 7680

// ---- device scratch (allocation-free rule) ----
__device__ __half g_A[(size_t)MROWS * DIM];          // fp16 normalized images   18.9 MB
__device__ __half g_B[(size_t)NCOLS * DIM];          // fp16 normalized words    15.7 MB
__device__ float  g_colmax[(size_t)BATCH * NCOLS];   // masked max over regions  7.9 MB
__device__ float  g_scores[BATCH * BATCH];
__device__ float  g_red[BATCH];
__device__ int    g_cnt = 0;                         // self-resetting block counter

__device__ __forceinline__ uint32_t s2u(const void* p) {
    return (uint32_t)__cvta_generic_to_shared(p);
}

// ============================================================================
// Kernel 1: L2-normalize + slice + fp16 convert (both tensors, one launch).
// ============================================================================
__global__ void norm_kernel(const float* __restrict__ im_in, const float* __restrict__ s_in)
{
    int ob = blockIdx.x;
    int which = (ob >= MROWS);
    const float* in = which ? s_in : im_in;
    int Lin  = which ? L_S : L_IM;
    int Lout = which ? LS  : LI;
    if (which) ob -= MROWS;
    int b = ob / Lout;
    int i = ob % Lout;
    const float4* src = (const float4*)(in + ((size_t)b * Lin + i + 1) * DIM);
    float4 v = src[threadIdx.x];

    float ss = v.x*v.x + v.y*v.y + v.z*v.z + v.w*v.w;
    #pragma unroll
    for (int o = 16; o > 0; o >>= 1) ss += __shfl_down_sync(0xffffffffu, ss, o);

    __shared__ float warp_s[8];
    __shared__ float inv_s;
    if ((threadIdx.x & 31) == 0) warp_s[threadIdx.x >> 5] = ss;
    __syncthreads();
    if (threadIdx.x == 0) {
        float tot = 0.f;
        #pragma unroll
        for (int q = 0; q < 8; q++) tot += warp_s[q];
        inv_s = 1.0f / fmaxf(sqrtf(tot), 1e-12f);
    }
    __syncthreads();
    float inv = inv_s;

    __half2 h01 = __floats2half2_rn(v.x * inv, v.y * inv);
    __half2 h23 = __floats2half2_rn(v.z * inv, v.w * inv);
    __half* dst = (which ? g_B : g_A) + (size_t)ob * DIM + 4 * threadIdx.x;
    *(__half2*)(dst)     = h01;
    *(__half2*)(dst + 2) = h23;
}

// ============================================================================
// Kernel 2: fp16 mma.sync GEMM with FUSED masked max-over-regions epilogue.
//   CTA 144x128x32 (4 images), 192 threads, occ 2, 6 warps of 48x64,
//   6-stage cp.async pipeline, compact 64B swizzled smem rows,
//   software-pipelined fragment loads within each k-tile.
// ============================================================================
#define BM 144
#define BN 128
#define BKH 32
#define STAGES 6
#define ROWB 64
#define STAGE_BYTES ((BM + BN) * ROWB)   // 17408
#define KTILES (DIM / BKH)               // 32
#define NTH 192
#define ESTR 132
#define SMEM_SZ (STAGES * STAGE_BYTES)   // 104448

__device__ __forceinline__ void cp16(uint32_t dst, const void* src) {
    asm volatile("cp.async.cg.shared.global [%0], [%1], 16;" :: "r"(dst), "l"(src));
}
__device__ __forceinline__ uint32_t swz(int row, int seg) {
    return (uint32_t)(row * ROWB + ((seg ^ ((row >> 1) & 3)) << 4));
}
#define LDSM4(r, addr) \
    asm volatile("ldmatrix.sync.aligned.m8n8.x4.shared.b16 {%0,%1,%2,%3}, [%4];" \
        : "=r"((r)[0]), "=r"((r)[1]), "=r"((r)[2]), "=r"((r)[3]) : "r"(addr))
#define HMMA(acc, a0, a1, a2, a3, b0, b1) \
    asm volatile("mma.sync.aligned.m16n8k16.row.col.f32.f16.f16.f32 " \
        "{%0,%1,%2,%3}, {%4,%5,%6,%7}, {%8,%9}, {%0,%1,%2,%3};" \
        : "+f"((acc)[0]), "+f"((acc)[1]), "+f"((acc)[2]), "+f"((acc)[3]) \
        : "r"(a0), "r"(a1), "r"(a2), "r"(a3), "r"(b0), "r"(b1))

__device__ __forceinline__ void load_stage(char* dsm, int slot, int m0, int n0, int kc, int t)
{
    char* As = dsm + slot * STAGE_BYTES;
    char* Bs = As + BM * ROWB;
    const __half* Agp = g_A + (size_t)m0 * DIM + kc * BKH;
    const __half* Bgp = g_B + (size_t)n0 * DIM + kc * BKH;
    #pragma unroll
    for (int i = 0; i < 3; i++) {
        int idx = t + i * NTH;
        int row = idx >> 2, seg = idx & 3;
        cp16(s2u(As + swz(row, seg)), Agp + (size_t)row * DIM + seg * 8);
    }
    #pragma unroll
    for (int i = 0; i < 3; i++) {
        int idx = t + i * NTH;
        if (idx < 512) {
            int row = idx >> 2, seg = idx & 3;
            cp16(s2u(Bs + swz(row, seg)), Bgp + (size_t)row * DIM + seg * 8);
        }
    }
}

__global__ __launch_bounds__(NTH, 2) void gemm_kernel(const int* __restrict__ im_len)
{
    extern __shared__ __align__(128) char dsm[];
    const int t   = threadIdx.x;
    const int wid = t >> 5, lid = t & 31;
    const int warp_m = (wid % 3) * 48;
    const int warp_n = (wid / 3) * 64;
    const int m0 = blockIdx.y * BM;
    const int n0 = blockIdx.x * BN;

    float acc[3][8][4];
    #pragma unroll
    for (int mf = 0; mf < 3; mf++)
        #pragma unroll
        for (int nf = 0; nf < 8; nf++)
            #pragma unroll
            for (int q = 0; q < 4; q++) acc[mf][nf][q] = 0.f;

    #pragma unroll
    for (int s = 0; s < STAGES - 1; s++) {
        load_stage(dsm, s, m0, n0, s, t);
        asm volatile("cp.async.commit_group;");
    }

    int rowA[3], swzA[3];
    #pragma unroll
    for (int mf = 0; mf < 3; mf++) {
        rowA[mf] = warp_m + mf * 16 + (lid & 15);
        swzA[mf] = (rowA[mf] >> 1) & 3;
    }
    const int a_seg0 = (lid >> 4);
    const int b_row_base = warp_n + ((lid >> 4) & 1) * 8 + (lid & 7);
    const int b_seg0 = (lid >> 3) & 1;

    int slot = 0, lslot = STAGES - 1;
    for (int j = 0; j < KTILES; j++) {
        if (j < KTILES - 4)       asm volatile("cp.async.wait_group 4;");
        else if (j == KTILES - 4) asm volatile("cp.async.wait_group 3;");
        else if (j == KTILES - 3) asm volatile("cp.async.wait_group 2;");
        else if (j == KTILES - 2) asm volatile("cp.async.wait_group 1;");
        else                      asm volatile("cp.async.wait_group 0;");
        __syncthreads();

        int jl = j + STAGES - 1;
        if (jl < KTILES) {
            load_stage(dsm, lslot, m0, n0, jl, t);
            asm volatile("cp.async.commit_group;");
        }

        const uint32_t AsU = s2u(dsm) + slot * STAGE_BYTES;
        const uint32_t BsU = AsU + BM * ROWB;

        uint32_t a0[3][4], a1[3][4], b0[4][4], b1[4][4];
        // --- front-load: ks0 A, ks0 B, ks1 B ---
        #pragma unroll
        for (int mf = 0; mf < 3; mf++)
            LDSM4(a0[mf], AsU + rowA[mf] * ROWB + ((a_seg0 ^ swzA[mf]) << 4));
        #pragma unroll
        for (int np = 0; np < 4; np++) {
            int row = b_row_base + np * 16;
            int sw = (row >> 1) & 3;
            LDSM4(b0[np], BsU + row * ROWB + ((b_seg0 ^ sw) << 4));
            LDSM4(b1[np], BsU + row * ROWB + (((b_seg0 + 2) ^ sw) << 4));
        }
        // --- ks0 HMMA nf 0..3 ---
        #pragma unroll
        for (int nf = 0; nf < 4; nf++) {
            uint32_t bb0 = b0[nf >> 1][(nf & 1) * 2], bb1 = b0[nf >> 1][(nf & 1) * 2 + 1];
            #pragma unroll
            for (int mf = 0; mf < 3; mf++)
                HMMA(acc[mf][nf], a0[mf][0], a0[mf][1], a0[mf][2], a0[mf][3], bb0, bb1);
        }
        // --- ks1 A loads (hidden under ks0 nf 4..7) ---
        #pragma unroll
        for (int mf = 0; mf < 3; mf++)
            LDSM4(a1[mf], AsU + rowA[mf] * ROWB + (((a_seg0 + 2) ^ swzA[mf]) << 4));
        // --- ks0 HMMA nf 4..7 ---
        #pragma unroll
        for (int nf = 4; nf < 8; nf++) {
            uint32_t bb0 = b0[nf >> 1][(nf & 1) * 2], bb1 = b0[nf >> 1][(nf & 1) * 2 + 1];
            #pragma unroll
            for (int mf = 0; mf < 3; mf++)
                HMMA(acc[mf][nf], a0[mf][0], a0[mf][1], a0[mf][2], a0[mf][3], bb0, bb1);
        }
        // --- ks1 HMMA nf 0..7 ---
        #pragma unroll
        for (int nf = 0; nf < 8; nf++) {
            uint32_t bb0 = b1[nf >> 1][(nf & 1) * 2], bb1 = b1[nf >> 1][(nf & 1) * 2 + 1];
            #pragma unroll
            for (int mf = 0; mf < 3; mf++)
                HMMA(acc[mf][nf], a1[mf][0], a1[mf][1], a1[mf][2], a1[mf][3], bb0, bb1);
        }

        slot  = (slot  == STAGES - 1) ? 0 : slot + 1;
        lslot = (lslot == STAGES - 1) ? 0 : lslot + 1;
    }

    // ---- fused epilogue: accs -> smem fp32 tile [144][128] (stride ESTR) ----
    __syncthreads();
    float* etile = (float*)dsm;
    const int r0 = warp_m + (lid >> 2);
    const int c0 = warp_n + (lid & 3) * 2;
    #pragma unroll
    for (int mf = 0; mf < 3; mf++) {
        #pragma unroll
        for (int nf = 0; nf < 8; nf++) {
            int r = r0 + mf * 16;
            int c = c0 + nf * 8;
            etile[r * ESTR + c]           = acc[mf][nf][0];
            etile[r * ESTR + c + 1]       = acc[mf][nf][1];
            etile[(r + 8) * ESTR + c]     = acc[mf][nf][2];
            etile[(r + 8) * ESTR + c + 1] = acc[mf][nf][3];
        }
    }
    __syncthreads();

    const int bimg0 = blockIdx.y * 4;
    for (int idx = t; idx < 512; idx += NTH) {
        int img = idx >> 7, col = idx & 127;
        int iml = im_len[bimg0 + img] - 1;
        const float* colp = etile + img * 36 * ESTR + col;
        float m = -1e30f;
        for (int r = 0; r < iml; r++) m = fmaxf(m, colp[r * ESTR]);
        if (iml < LI) m = fmaxf(m, 0.f);
        g_colmax[(size_t)(bimg0 + img) * NCOLS + n0 + col] = m;
    }
}

// ============================================================================
// Kernel 3: scores[b][c] = sum_{j < sl} colmax[b][c*30+j].
// ============================================================================
__global__ __launch_bounds__(256) void score_kernel(const int* __restrict__ s_len)
{
    __shared__ float row[NCOLS];
    const int b = blockIdx.x, t = threadIdx.x;
    const float4* src = (const float4*)(g_colmax + (size_t)b * NCOLS);
    #pragma unroll
    for (int i = 0; i < 8; i++) {
        int idx = t + i * 256;
        if (idx < NCOLS / 4)
            *(float4*)(row + 4 * idx) = src[idx];
    }
    __syncthreads();

    int sl = s_len[t] - 3;
    if (sl > LS) sl = LS;
    if (sl < 0)  sl = 0;
    const float* p = row + t * LS;
    float sum = 0.f;
    for (int j = 0; j < sl; j++) sum += p[j];
    g_scores[b * BATCH + t] = sum;
}

// ============================================================================
// Kernel 4: fused contrastive loss (last block reduces; counter self-resets)
// ============================================================================
__global__ void loss_kernel(float* __restrict__ out)
{
    int b = blockIdx.x, t = threadIdx.x;
    __shared__ float sd;
    __shared__ float w1[8], w2[8];
    if (t == 0) sd = g_scores[b * BATCH + b];
    __syncthreads();
    float d = sd;
    float v1 = 0.f, v2 = 0.f;
    if (t != b) {
        v1 = fmaxf(0.f, MARGIN + g_scores[b * BATCH + t] - d);
        v2 = fmaxf(0.f, MARGIN + g_scores[t * BATCH + b] - d);
    }
    #pragma unroll
    for (int o = 16; o > 0; o >>= 1) {
        v1 = fmaxf(v1, __shfl_down_sync(0xffffffffu, v1, o));
        v2 = fmaxf(v2, __shfl_down_sync(0xffffffffu, v2, o));
    }
    if ((t & 31) == 0) { w1[t >> 5] = v1; w2[t >> 5] = v2; }
    __syncthreads();

    __shared__ int is_last;
    if (t == 0) {
        float m1 = w1[0], m2 = w2[0];
        #pragma unroll
        for (int q = 1; q < 8; q++) { m1 = fmaxf(m1, w1[q]); m2 = fmaxf(m2, w2[q]); }
        g_red[b] = m1 + m2;
        __threadfence();
        is_last = (atomicAdd(&g_cnt, 1) == BATCH - 1);
    }
    __syncthreads();
    if (is_last) {
        __shared__ float sm[BATCH];
        sm[t] = g_red[t];
        __syncthreads();
        #pragma unroll
        for (int o = 128; o > 0; o >>= 1) {
            if (t < o) sm[t] += sm[t + o];
            __syncthreads();
        }
        if (t == 0) { out[0] = sm[0]; g_cnt = 0; }   // reset: graph-replay safe
    }
}

// ============================================================================
extern "C" void kernel_launch(void* const* d_in, const int* in_sizes, int n_in,
                              void* d_out, int out_size)
{
    const float* im_set = (const float*)d_in[0];
    const float* s_seq  = (const float*)d_in[1];
    const int*   im_len = (const int*)d_in[2];
    const int*   s_len  = (const int*)d_in[3];
    float* out = (float*)d_out;

    cudaFuncSetAttribute(gemm_kernel, cudaFuncAttributeMaxDynamicSharedMemorySize,
                         SMEM_SZ);

    norm_kernel<<<BATCH * LI + BATCH * LS, 256>>>(im_set, s_seq);

    dim3 grid(NCOLS / BN, MROWS / BM);   // (60, 64)
    gemm_kernel<<<grid, NTH, SMEM_SZ>>>(im_len);

    score_kernel<<<BATCH, 256>>>(s_len);

    loss_kernel<<<BATCH, 256>>>(out);
}

// round 11
// speedup vs baseline: 1.0345x; 1.0345x over previous
#include <cuda_runtime.h>
#include <cuda_fp16.h>
#include <math.h>
#include <stdint.h>

// Problem constants
#define BATCH 256
#define DIM   1024
#define L_IM  37
#define L_S   33
#define LI    36
#define LS    30
#define MARGIN 0.2f

#define MROWS  (BATCH*LI)     // 9216
#define NCOLS  (BATCH*LS)     // 7680

// ---- device scratch (allocation-free rule) ----
__device__ __half g_A[(size_t)MROWS * DIM];
__device__ __half g_B[(size_t)NCOLS * DIM];
__device__ float  g_colmax[(size_t)BATCH * NCOLS];
__device__ float  g_scores[BATCH * BATCH];
__device__ float  g_red[BATCH];
__device__ int    g_cnt = 0;

__device__ __forceinline__ uint32_t s2u(const void* p) {
    return (uint32_t)__cvta_generic_to_shared(p);
}

// ============================================================================
// Kernel 1: L2-normalize + slice + fp16 convert (both tensors, one launch).
// ============================================================================
__global__ void norm_kernel(const float* __restrict__ im_in, const float* __restrict__ s_in)
{
    int ob = blockIdx.x;
    int which = (ob >= MROWS);
    const float* in = which ? s_in : im_in;
    int Lin  = which ? L_S : L_IM;
    int Lout = which ? LS  : LI;
    if (which) ob -= MROWS;
    int b = ob / Lout;
    int i = ob % Lout;
    const float4* src = (const float4*)(in + ((size_t)b * Lin + i + 1) * DIM);
    float4 v = src[threadIdx.x];

    float ss = v.x*v.x + v.y*v.y + v.z*v.z + v.w*v.w;
    #pragma unroll
    for (int o = 16; o > 0; o >>= 1) ss += __shfl_down_sync(0xffffffffu, ss, o);

    __shared__ float warp_s[8];
    __shared__ float inv_s;
    if ((threadIdx.x & 31) == 0) warp_s[threadIdx.x >> 5] = ss;
    __syncthreads();
    if (threadIdx.x == 0) {
        float tot = 0.f;
        #pragma unroll
        for (int q = 0; q < 8; q++) tot += warp_s[q];
        inv_s = 1.0f / fmaxf(sqrtf(tot), 1e-12f);
    }
    __syncthreads();
    float inv = inv_s;

    __half2 h01 = __floats2half2_rn(v.x * inv, v.y * inv);
    __half2 h23 = __floats2half2_rn(v.z * inv, v.w * inv);
    __half* dst = (which ? g_B : g_A) + (size_t)ob * DIM + 4 * threadIdx.x;
    *(__half2*)(dst)     = h01;
    *(__half2*)(dst + 2) = h23;
}

// ============================================================================
// Kernel 2: fp16 mma.sync GEMM with FUSED masked max-over-regions epilogue.
//   CTA 144x128x64 (4 images), 192 threads, occ 2, 6 warps of 48x64,
//   3-stage cp.async pipeline of 64-K chunks (same bytes in flight as
//   R9's 6x32, but HALF the barrier count), canonical SW128 swizzle.
//   Mainloop body shape identical to R9 (ptxas schedules best).
// ============================================================================
#define BM 144
#define BN 128
#define BKH 64                       // K halfs per stage (one 128B row)
#define STAGES 3
#define ROWB 128
#define STAGE_BYTES ((BM + BN) * ROWB)   // 34816
#define KTILES (DIM / BKH)               // 16
#define NTH 192
#define ESTR 132
#define SMEM_SZ (STAGES * STAGE_BYTES)   // 104448

__device__ __forceinline__ void cp16(uint32_t dst, const void* src) {
    asm volatile("cp.async.cg.shared.global [%0], [%1], 16;" :: "r"(dst), "l"(src));
}
// canonical SW128: 16B segment seg (0..7) in row, phys = seg ^ (row & 7)
__device__ __forceinline__ uint32_t swz(int row, int seg) {
    return (uint32_t)(row * ROWB + ((seg ^ (row & 7)) << 4));
}
#define LDSM4(r, addr) \
    asm volatile("ldmatrix.sync.aligned.m8n8.x4.shared.b16 {%0,%1,%2,%3}, [%4];" \
        : "=r"((r)[0]), "=r"((r)[1]), "=r"((r)[2]), "=r"((r)[3]) : "r"(addr))
#define HMMA(acc, a0, a1, a2, a3, b0, b1) \
    asm volatile("mma.sync.aligned.m16n8k16.row.col.f32.f16.f16.f32 " \
        "{%0,%1,%2,%3}, {%4,%5,%6,%7}, {%8,%9}, {%0,%1,%2,%3};" \
        : "+f"((acc)[0]), "+f"((acc)[1]), "+f"((acc)[2]), "+f"((acc)[3]) \
        : "r"(a0), "r"(a1), "r"(a2), "r"(a3), "r"(b0), "r"(b1))

__device__ __forceinline__ void load_stage(char* dsm, int slot, int m0, int n0, int kc, int t)
{
    char* As = dsm + slot * STAGE_BYTES;
    char* Bs = As + BM * ROWB;
    const __half* Agp = g_A + (size_t)m0 * DIM + kc * BKH;
    const __half* Bgp = g_B + (size_t)n0 * DIM + kc * BKH;
    #pragma unroll
    for (int i = 0; i < 6; i++) {                 // 1152 A-vectors
        int idx = t + i * NTH;
        int row = idx >> 3, seg = idx & 7;
        cp16(s2u(As + swz(row, seg)), Agp + (size_t)row * DIM + seg * 8);
    }
    #pragma unroll
    for (int i = 0; i < 6; i++) {                 // 1024 B-vectors (guarded)
        int idx = t + i * NTH;
        if (idx < 1024) {
            int row = idx >> 3, seg = idx & 7;
            cp16(s2u(Bs + swz(row, seg)), Bgp + (size_t)row * DIM + seg * 8);
        }
    }
}

__global__ __launch_bounds__(NTH, 2) void gemm_kernel(const int* __restrict__ im_len)
{
    extern __shared__ __align__(128) char dsm[];
    const int t   = threadIdx.x;
    const int wid = t >> 5, lid = t & 31;
    const int warp_m = (wid % 3) * 48;
    const int warp_n = (wid / 3) * 64;
    const int m0 = blockIdx.y * BM;
    const int n0 = blockIdx.x * BN;

    float acc[3][8][4];
    #pragma unroll
    for (int mf = 0; mf < 3; mf++)
        #pragma unroll
        for (int nf = 0; nf < 8; nf++)
            #pragma unroll
            for (int q = 0; q < 4; q++) acc[mf][nf][q] = 0.f;

    #pragma unroll
    for (int s = 0; s < STAGES - 1; s++) {        // fill stages 0,1
        load_stage(dsm, s, m0, n0, s, t);
        asm volatile("cp.async.commit_group;");
    }

    int rowA[3], rswA[3];
    #pragma unroll
    for (int mf = 0; mf < 3; mf++) {
        rowA[mf] = warp_m + mf * 16 + (lid & 15);
        rswA[mf] = rowA[mf] & 7;
    }
    const int a_seg0 = (lid >> 4);                     // + 2*ks -> 0..7
    const int b_row_base = warp_n + ((lid >> 4) & 1) * 8 + (lid & 7);
    const int b_seg0 = (lid >> 3) & 1;                 // + 2*ks -> 0..7

    int slot = 0, lslot = STAGES - 1;
    for (int j = 0; j < KTILES; j++) {
        if (j < KTILES - 1) asm volatile("cp.async.wait_group 1;");
        else                asm volatile("cp.async.wait_group 0;");
        __syncthreads();

        int jl = j + STAGES - 1;
        if (jl < KTILES) {
            load_stage(dsm, lslot, m0, n0, jl, t);
            asm volatile("cp.async.commit_group;");
        }

        const uint32_t AsU = s2u(dsm) + slot * STAGE_BYTES;
        const uint32_t BsU = AsU + BM * ROWB;

        #pragma unroll
        for (int ks = 0; ks < 4; ks++) {
            uint32_t a[3][4];
            #pragma unroll
            for (int mf = 0; mf < 3; mf++)
                LDSM4(a[mf], AsU + rowA[mf] * ROWB
                             + (((a_seg0 + 2 * ks) ^ rswA[mf]) << 4));
            uint32_t bf[4][4];
            #pragma unroll
            for (int np = 0; np < 4; np++) {
                int row = b_row_base + np * 16;
                LDSM4(bf[np], BsU + row * ROWB
                              + (((b_seg0 + 2 * ks) ^ (row & 7)) << 4));
            }
            #pragma unroll
            for (int nf = 0; nf < 8; nf++) {
                uint32_t b0 = bf[nf >> 1][(nf & 1) * 2];
                uint32_t b1 = bf[nf >> 1][(nf & 1) * 2 + 1];
                #pragma unroll
                for (int mf = 0; mf < 3; mf++)
                    HMMA(acc[mf][nf], a[mf][0], a[mf][1], a[mf][2], a[mf][3], b0, b1);
            }
        }
        slot  = (slot  == STAGES - 1) ? 0 : slot + 1;
        lslot = (lslot == STAGES - 1) ? 0 : lslot + 1;
    }

    // ---- fused epilogue: accs -> smem fp32 tile [144][128] (stride ESTR) ----
    __syncthreads();
    float* etile = (float*)dsm;            // 76032 B < SMEM_SZ
    const int r0 = warp_m + (lid >> 2);
    const int c0 = warp_n + (lid & 3) * 2;
    #pragma unroll
    for (int mf = 0; mf < 3; mf++) {
        #pragma unroll
        for (int nf = 0; nf < 8; nf++) {
            int r = r0 + mf * 16;
            int c = c0 + nf * 8;
            etile[r * ESTR + c]           = acc[mf][nf][0];
            etile[r * ESTR + c + 1]       = acc[mf][nf][1];
            etile[(r + 8) * ESTR + c]     = acc[mf][nf][2];
            etile[(r + 8) * ESTR + c + 1] = acc[mf][nf][3];
        }
    }
    __syncthreads();

    const int bimg0 = blockIdx.y * 4;
    for (int idx = t; idx < 512; idx += NTH) {
        int img = idx >> 7, col = idx & 127;
        int iml = im_len[bimg0 + img] - 1;
        const float* colp = etile + img * 36 * ESTR + col;
        float m = -1e30f;
        for (int r = 0; r < iml; r++) m = fmaxf(m, colp[r * ESTR]);
        if (iml < LI) m = fmaxf(m, 0.f);
        g_colmax[(size_t)(bimg0 + img) * NCOLS + n0 + col] = m;
    }
}

// ============================================================================
// Kernel 3: scores[b][c] = sum_{j < sl} colmax[b][c*30+j].
// ============================================================================
__global__ __launch_bounds__(256) void score_kernel(const int* __restrict__ s_len)
{
    __shared__ float row[NCOLS];
    const int b = blockIdx.x, t = threadIdx.x;
    const float4* src = (const float4*)(g_colmax + (size_t)b * NCOLS);
    #pragma unroll
    for (int i = 0; i < 8; i++) {
        int idx = t + i * 256;
        if (idx < NCOLS / 4)
            *(float4*)(row + 4 * idx) = src[idx];
    }
    __syncthreads();

    int sl = s_len[t] - 3;
    if (sl > LS) sl = LS;
    if (sl < 0)  sl = 0;
    const float* p = row + t * LS;
    float sum = 0.f;
    for (int j = 0; j < sl; j++) sum += p[j];
    g_scores[b * BATCH + t] = sum;
}

// ============================================================================
// Kernel 4: fused contrastive loss (last block reduces; counter self-resets)
// ============================================================================
__global__ void loss_kernel(float* __restrict__ out)
{
    int b = blockIdx.x, t = threadIdx.x;
    __shared__ float sd;
    __shared__ float w1[8], w2[8];
    if (t == 0) sd = g_scores[b * BATCH + b];
    __syncthreads();
    float d = sd;
    float v1 = 0.f, v2 = 0.f;
    if (t != b) {
        v1 = fmaxf(0.f, MARGIN + g_scores[b * BATCH + t] - d);
        v2 = fmaxf(0.f, MARGIN + g_scores[t * BATCH + b] - d);
    }
    #pragma unroll
    for (int o = 16; o > 0; o >>= 1) {
        v1 = fmaxf(v1, __shfl_down_sync(0xffffffffu, v1, o));
        v2 = fmaxf(v2, __shfl_down_sync(0xffffffffu, v2, o));
    }
    if ((t & 31) == 0) { w1[t >> 5] = v1; w2[t >> 5] = v2; }
    __syncthreads();

    __shared__ int is_last;
    if (t == 0) {
        float m1 = w1[0], m2 = w2[0];
        #pragma unroll
        for (int q = 1; q < 8; q++) { m1 = fmaxf(m1, w1[q]); m2 = fmaxf(m2, w2[q]); }
        g_red[b] = m1 + m2;
        __threadfence();
        is_last = (atomicAdd(&g_cnt, 1) == BATCH - 1);
    }
    __syncthreads();
    if (is_last) {
        __shared__ float sm[BATCH];
        sm[t] = g_red[t];
        __syncthreads();
        #pragma unroll
        for (int o = 128; o > 0; o >>= 1) {
            if (t < o) sm[t] += sm[t + o];
            __syncthreads();
        }
        if (t == 0) { out[0] = sm[0]; g_cnt = 0; }
    }
}

// ============================================================================
extern "C" void kernel_launch(void* const* d_in, const int* in_sizes, int n_in,
                              void* d_out, int out_size)
{
    const float* im_set = (const float*)d_in[0];
    const float* s_seq  = (const float*)d_in[1];
    const int*   im_len = (const int*)d_in[2];
    const int*   s_len  = (const int*)d_in[3];
    float* out = (float*)d_out;

    cudaFuncSetAttribute(gemm_kernel, cudaFuncAttributeMaxDynamicSharedMemorySize,
                         SMEM_SZ);

    norm_kernel<<<BATCH * LI + BATCH * LS, 256>>>(im_set, s_seq);

    dim3 grid(NCOLS / BN, MROWS / BM);   // (60, 64)
    gemm_kernel<<<grid, NTH, SMEM_SZ>>>(im_len);

    score_kernel<<<BATCH, 256>>>(s_len);

    loss_kernel<<<BATCH, 256>>>(out);
}